// round 14
// baseline (speedup 1.0000x reference)
#include <cuda_runtime.h>
#include <cstdint>

// Problem constants
#define RES    64
#define C_CH   8
#define NB     64
#define CORE   32
#define POS    16                        // (RES-CORE)/2
#define DIM    (CORE*CORE*CORE*C_CH)     // 262144
#define BATCH  32
#define VOL    (RES*RES*RES)             // 262144 floats per (b,c) volume
#define BSTRIDE (C_CH*VOL)               // 2097152 floats per batch
#define BSTRIDE4 (BSTRIDE/4)
#define VOL4     (VOL/4)
#define SLABF   (RES*RES)                // 4096 floats per i-slab

#define TPB 256
#define BPB 8                            // batches per block
#define DPT 4                            // d per thread (one LDG.128 of U)
#define NBLOCKS ((DIM/(TPB*DPT)) * (BATCH/BPB))   // 256 stripes * 4 = 1024

// ---- packed fp32x2 helpers (sm_10x FFMA2) ----
__device__ __forceinline__ unsigned long long pack2(float lo, float hi) {
    unsigned long long r;
    asm("mov.b64 %0, {%1, %2};" : "=l"(r) : "f"(lo), "f"(hi));
    return r;
}
__device__ __forceinline__ unsigned long long fma2(unsigned long long a,
                                                   unsigned long long b,
                                                   unsigned long long c) {
    unsigned long long r;
    asm("fma.rn.f32x2 %0, %1, %2, %3;" : "=l"(r) : "l"(a), "l"(b), "l"(c));
    return r;
}

// ---- L2 cache policies via createpolicy (legal with any ld/st width) ----
__device__ __forceinline__ unsigned long long policy_evict_last() {
    unsigned long long p;
    asm("createpolicy.fractional.L2::evict_last.b64 %0, 1.0;" : "=l"(p));
    return p;
}
__device__ __forceinline__ unsigned long long policy_evict_first() {
    unsigned long long p;
    asm("createpolicy.fractional.L2::evict_first.b64 %0, 1.0;" : "=l"(p));
    return p;
}
// U load pinned toward L2 residency across graph replays (67 MB < 126 MB L2).
__device__ __forceinline__ float4 ldg_hint4(const float4* p, unsigned long long pol) {
    float4 v;
    asm volatile("ld.global.nc.L2::cache_hint.v4.f32 {%0,%1,%2,%3}, [%4], %5;"
                 : "=f"(v.x), "=f"(v.y), "=f"(v.z), "=f"(v.w) : "l"(p), "l"(pol));
    return v;
}
// Write-once output stores yield L2 to U.
__device__ __forceinline__ void stg_hint4(float4* p, float4 v, unsigned long long pol) {
    asm volatile("st.global.L2::cache_hint.v4.f32 [%0], {%1,%2,%3,%4}, %5;"
                 :: "l"(p), "f"(v.x), "f"(v.y), "f"(v.z), "f"(v.w), "l"(pol) : "memory");
}
__device__ __forceinline__ void stg_hint_u64x2(void* p, unsigned long long r0,
                                               unsigned long long r1,
                                               unsigned long long pol) {
    asm volatile("st.global.L2::cache_hint.v2.b64 [%0], {%1,%2}, %3;"
                 :: "l"(p), "l"(r0), "l"(r1), "l"(pol) : "memory");
}

// Fused kernel (R10 structure + L2 cache-policy hints):
//   * periphery zeroed via cp.async.bulk (4 KB from SMEM zero buffer), 6 ops
//     per GEMM chunk so the async write stream is continuous.
//   * ragged k-edges zeroed with one evict_first-hint STG.128/thread/chunk.
//   * GEMM: thread = 4 consecutive d x 8 batches, f32x2 accumulators;
//     U loads evict_last so U stays L2-resident across graph replays
//     -> steady-state DRAM traffic ~= pure 268 MB write stream.
__global__ __launch_bounds__(TPB, 3)
void core_part_fused(const float* __restrict__ z,
                     const float* __restrict__ U,
                     const float* __restrict__ L,
                     const float* __restrict__ mu,
                     float* __restrict__ out) {
    __shared__ __align__(16) float zbuf[1024];      // 4 KB of zeros (bulk-copy source)
    __shared__ __align__(16) float a_s[NB * BPB];   // 2 KB coefficients

    const unsigned tid = threadIdx.x;
    const unsigned stripe = blockIdx.x >> 2;        // 0..255 -> (c, i)
    const unsigned bg     = (blockIdx.x & 3) * BPB; // 0/8/16/24
    const unsigned cc = stripe >> 5;                // channel 0..7
    const unsigned ii = stripe & 31;                // core i 0..31
    const unsigned iful = (ii < 16) ? ii : ii + 32; // adopted full-periphery slab

    const float4 zz = make_float4(0.f, 0.f, 0.f, 0.f);
    float4* out4 = reinterpret_cast<float4*>(out);

    const unsigned long long pol_last  = policy_evict_last();
    const unsigned long long pol_first = policy_evict_first();

    // ---- prologue: stage zeros + coefficients ----
    reinterpret_cast<float4*>(zbuf)[tid] = zz;      // 256 f4 = 4 KB
    #pragma unroll
    for (unsigned idx = tid; idx < NB * BPB; idx += TPB) {
        unsigned n  = idx >> 3;
        unsigned bl = idx & 7;
        a_s[idx] = L[n] * z[(bg + bl) * NB + n];
    }
    __syncthreads();

    // Per-thread TMA role: threads 0..5 each own one 4 KB periphery piece per batch.
    const unsigned zsm = (unsigned)__cvta_generic_to_shared(zbuf);
    size_t tma_off = 0;
    const bool tma_thread = (tid < 6);
    if (tma_thread) {
        if (tid < 4)       tma_off = (size_t)cc * VOL + iful * SLABF + tid * 1024;
        else if (tid == 4) tma_off = (size_t)cc * VOL + (ii + POS) * SLABF;
        else               tma_off = (size_t)cc * VOL + (ii + POS) * SLABF + 3072;
        asm volatile("fence.proxy.async.shared::cta;" ::: "memory");
    }

    // ---- GEMM mainloop; each chunk zeroes one batch's periphery ----
    const unsigned du = stripe * TPB + tid;         // f4-index into U row

    unsigned long long acc0[BPB], acc1[BPB];        // per batch: d0d1, d2d3
    #pragma unroll
    for (int b = 0; b < BPB; b++) { acc0[b] = 0ull; acc1[b] = 0ull; }

    const float4* U4 = reinterpret_cast<const float4*>(U);
    const float4* a4 = reinterpret_cast<const float4*>(a_s);  // 2 per n

    // k-edge geometry for this thread (same every chunk, batch varies)
    const unsigned erow = tid >> 3;                 // 0..31
    const unsigned eq   = tid & 7;
    const unsigned ek4  = (eq < 4) ? eq : eq + 8;   // f4 col 0-3 / 12-15
    const unsigned ebase = cc * (unsigned)VOL4 + (ii + POS) * 1024 + erow * 16 + ek4;

    #pragma unroll
    for (unsigned chunk = 0; chunk < 8; chunk++) {
        const unsigned bat = bg + chunk;

        // 6 bulk zero-stores for batch `bat` (async; drains during this chunk)
        if (tma_thread) {
            asm volatile(
                "cp.async.bulk.global.shared::cta.bulk_group [%0], [%1], %2;\n\t"
                "cp.async.bulk.commit_group;"
                :: "l"(out + (size_t)bat * BSTRIDE + tma_off), "r"(zsm), "n"(4096)
                : "memory");
        }

        // one ragged k-edge zero store (batch bat), evict_first hint
        stg_hint4(&out4[bat * (unsigned)BSTRIDE4 + ebase], zz, pol_first);

        #pragma unroll
        for (unsigned nn = 0; nn < 8; nn++) {
            const unsigned n = chunk * 8 + nn;
            float4 uv = ldg_hint4(&U4[n * (unsigned)(DIM / 4) + du], pol_last);
            unsigned long long u01 = pack2(uv.x, uv.y);
            unsigned long long u23 = pack2(uv.z, uv.w);
            float4 alo = a4[n * 2 + 0];             // coefficients, batches 0..3
            float4 ahi = a4[n * 2 + 1];             // batches 4..7
            unsigned long long ab;
            ab = pack2(alo.x, alo.x); acc0[0]=fma2(u01,ab,acc0[0]); acc1[0]=fma2(u23,ab,acc1[0]);
            ab = pack2(alo.y, alo.y); acc0[1]=fma2(u01,ab,acc0[1]); acc1[1]=fma2(u23,ab,acc1[1]);
            ab = pack2(alo.z, alo.z); acc0[2]=fma2(u01,ab,acc0[2]); acc1[2]=fma2(u23,ab,acc1[2]);
            ab = pack2(alo.w, alo.w); acc0[3]=fma2(u01,ab,acc0[3]); acc1[3]=fma2(u23,ab,acc1[3]);
            ab = pack2(ahi.x, ahi.x); acc0[4]=fma2(u01,ab,acc0[4]); acc1[4]=fma2(u23,ab,acc1[4]);
            ab = pack2(ahi.y, ahi.y); acc0[5]=fma2(u01,ab,acc0[5]); acc1[5]=fma2(u23,ab,acc1[5]);
            ab = pack2(ahi.z, ahi.z); acc0[6]=fma2(u01,ab,acc0[6]); acc1[6]=fma2(u23,ab,acc1[6]);
            ab = pack2(ahi.w, ahi.w); acc0[7]=fma2(u01,ab,acc0[7]); acc1[7]=fma2(u23,ab,acc1[7]);
        }
    }

    // ---- epilogue: add mu, store core (evict_first-hint STG.128, coalesced) ----
    const float4 mv = __ldg(&reinterpret_cast<const float4*>(mu)[du]);
    const unsigned long long m01 = pack2(mv.x, mv.y);
    const unsigned long long m23 = pack2(mv.z, mv.w);

    const unsigned d0 = du * DPT;
    const unsigned k = d0 & 31;                     // multiple of 4
    const unsigned j = (d0 >> 5) & 31;

    const unsigned base = cc * VOL
                        + (ii + POS) * (RES * RES)
                        + (j + POS) * RES
                        + (k + POS)
                        + bg * (unsigned)BSTRIDE;

    #pragma unroll
    for (int b = 0; b < BPB; b++) {
        unsigned long long r0, r1;
        asm("add.rn.f32x2 %0, %1, %2;" : "=l"(r0) : "l"(acc0[b]), "l"(m01));
        asm("add.rn.f32x2 %0, %1, %2;" : "=l"(r1) : "l"(acc1[b]), "l"(m23));
        stg_hint_u64x2(&out[base + (unsigned)b * BSTRIDE], r0, r1, pol_first);
    }

    // ---- ensure bulk zero-stores completed before block exit ----
    if (tma_thread) {
        asm volatile("cp.async.bulk.wait_group 0;" ::: "memory");
    }
}

extern "C" void kernel_launch(void* const* d_in, const int* in_sizes, int n_in,
                              void* d_out, int out_size) {
    const float* z  = (const float*)d_in[0];   // (32, 64)
    const float* U  = (const float*)d_in[1];   // (64, 262144)
    const float* L  = (const float*)d_in[2];   // (64,)
    const float* mu = (const float*)d_in[3];   // (262144,)
    float* out = (float*)d_out;                // (32, 8, 64, 64, 64)

    core_part_fused<<<NBLOCKS, TPB>>>(z, U, L, mu, out);
}

// round 15
// speedup vs baseline: 1.0885x; 1.0885x over previous
#include <cuda_runtime.h>
#include <cstdint>

// Problem constants
#define RES    64
#define C_CH   8
#define NB     64
#define CORE   32
#define POS    16                        // (RES-CORE)/2
#define DIM    (CORE*CORE*CORE*C_CH)     // 262144
#define BATCH  32
#define VOL    (RES*RES*RES)             // 262144 floats per (b,c) volume
#define BSTRIDE (C_CH*VOL)               // 2097152 floats per batch
#define BSTRIDE4 (BSTRIDE/4)
#define VOL4     (VOL/4)
#define SLABF   (RES*RES)                // 4096 floats per i-slab

#define TPB 256
#define BPB 8                            // batches per block
#define DPT 4                            // d per thread (16B of U per n)
#define NBLOCKS ((DIM/(TPB*DPT)) * (BATCH/BPB))   // 256 stripes * 4 = 1024

#define NGROUPS 16                       // software-pipeline groups
#define NPG 4                            // n per group (NGROUPS*NPG = 64 = NB)

// ---- packed fp32x2 helpers (sm_10x FFMA2) ----
__device__ __forceinline__ unsigned long long pack2(float lo, float hi) {
    unsigned long long r;
    asm("mov.b64 %0, {%1, %2};" : "=l"(r) : "f"(lo), "f"(hi));
    return r;
}
__device__ __forceinline__ void unpack2(unsigned long long v, float& lo, float& hi) {
    asm("mov.b64 {%0, %1}, %2;" : "=f"(lo), "=f"(hi) : "l"(v));
}
__device__ __forceinline__ unsigned long long fma2(unsigned long long a,
                                                   unsigned long long b,
                                                   unsigned long long c) {
    unsigned long long r;
    asm("fma.rn.f32x2 %0, %1, %2, %3;" : "=l"(r) : "l"(a), "l"(b), "l"(c));
    return r;
}
__device__ __forceinline__ unsigned long long add2(unsigned long long a,
                                                   unsigned long long b) {
    unsigned long long r;
    asm("add.rn.f32x2 %0, %1, %2;" : "=l"(r) : "l"(a), "l"(b));
    return r;
}

// Fused kernel, cp.async-pipelined:
//   * U streamed global->SMEM with cp.async.cg one group ahead (double buffer);
//     each thread consumes only its own 16B slots -> no extra syncs; LDG
//     latency leaves the critical path.
//   * accumulators pack BATCH-pairs: a coefficients load as f32x2 straight
//     from SMEM (no splat movs); 4 u-splats per n.
//   * periphery zeroed via cp.async.bulk (4 KB from SMEM zero buffer), one
//     batch's worth every 2 groups -> continuous async write stream.
//   * ragged k-edges: one STG.128/thread every 2 groups.
__global__ __launch_bounds__(TPB, 3)
void core_part_fused(const float* __restrict__ z,
                     const float* __restrict__ U,
                     const float* __restrict__ L,
                     const float* __restrict__ mu,
                     float* __restrict__ out) {
    __shared__ __align__(16) float4 u_s[2][NPG][TPB];   // 32 KB U pipeline
    __shared__ __align__(16) float zbuf[1024];          // 4 KB zeros (bulk source)
    __shared__ __align__(16) float a_s[NB * BPB];       // 2 KB coefficients

    const unsigned tid = threadIdx.x;
    const unsigned stripe = blockIdx.x >> 2;        // 0..255 -> (c, i)
    const unsigned bg     = (blockIdx.x & 3) * BPB; // 0/8/16/24
    const unsigned cc = stripe >> 5;                // channel 0..7
    const unsigned ii = stripe & 31;                // core i 0..31
    const unsigned iful = (ii < 16) ? ii : ii + 32; // adopted full-periphery slab

    const float4 zz = make_float4(0.f, 0.f, 0.f, 0.f);
    float4* out4 = reinterpret_cast<float4*>(out);

    // ---- prologue: stage zeros + coefficients (a_s[n*8+bl] = L[n]*z[bg+bl,n]) ----
    reinterpret_cast<float4*>(zbuf)[tid] = zz;
    #pragma unroll
    for (unsigned idx = tid; idx < NB * BPB; idx += TPB) {
        unsigned n  = idx >> 3;
        unsigned bl = idx & 7;
        a_s[idx] = L[n] * z[(bg + bl) * NB + n];
    }
    __syncthreads();

    // Per-thread TMA role: threads 0..5 each own one 4 KB periphery piece per batch.
    const unsigned zsm = (unsigned)__cvta_generic_to_shared(zbuf);
    size_t tma_off = 0;
    const bool tma_thread = (tid < 6);
    if (tma_thread) {
        if (tid < 4)       tma_off = (size_t)cc * VOL + iful * SLABF + tid * 1024;
        else if (tid == 4) tma_off = (size_t)cc * VOL + (ii + POS) * SLABF;
        else               tma_off = (size_t)cc * VOL + (ii + POS) * SLABF + 3072;
        asm volatile("fence.proxy.async.shared::cta;" ::: "memory");
    }

    const unsigned du = stripe * TPB + tid;         // f4-index into U row
    const float4* Ug = reinterpret_cast<const float4*>(U) + du;
    const unsigned us_base = (unsigned)__cvta_generic_to_shared(&u_s[0][0][tid]);

    // issue pipeline group 0
    #pragma unroll
    for (int nn = 0; nn < NPG; nn++) {
        asm volatile("cp.async.cg.shared.global [%0], [%1], 16;"
                     :: "r"(us_base + nn * TPB * 16),
                        "l"(Ug + (size_t)nn * (DIM / 4)) : "memory");
    }
    asm volatile("cp.async.commit_group;" ::: "memory");

    // accumulators: acc[d][p] = f32x2 {batch bg+2p, batch bg+2p+1} for local d
    unsigned long long acc[DPT][BPB / 2];
    #pragma unroll
    for (int dd = 0; dd < DPT; dd++)
        #pragma unroll
        for (int p = 0; p < BPB / 2; p++) acc[dd][p] = 0ull;

    const ulonglong2* a_u2 = reinterpret_cast<const ulonglong2*>(a_s); // 2 per n

    // k-edge geometry (same every time, batch varies)
    const unsigned erow = tid >> 3;                 // 0..31
    const unsigned eq   = tid & 7;
    const unsigned ek4  = (eq < 4) ? eq : eq + 8;
    const unsigned ebase = cc * (unsigned)VOL4 + (ii + POS) * 1024 + erow * 16 + ek4;

    #pragma unroll
    for (unsigned g = 0; g < NGROUPS; g++) {
        // prefetch next group
        if (g + 1 < NGROUPS) {
            const unsigned nb = (g + 1) & 1;
            #pragma unroll
            for (int nn = 0; nn < NPG; nn++) {
                asm volatile("cp.async.cg.shared.global [%0], [%1], 16;"
                             :: "r"(us_base + (nb * NPG + nn) * TPB * 16),
                                "l"(Ug + (size_t)((g + 1) * NPG + nn) * (DIM / 4))
                             : "memory");
            }
        }
        asm volatile("cp.async.commit_group;" ::: "memory");
        asm volatile("cp.async.wait_group 1;" ::: "memory");

        // every 2 groups: zero one batch's periphery (TMA bulk) + its k-edges
        if ((g & 1) == 0) {
            const unsigned bat = bg + (g >> 1);
            if (tma_thread) {
                asm volatile(
                    "cp.async.bulk.global.shared::cta.bulk_group [%0], [%1], %2;\n\t"
                    "cp.async.bulk.commit_group;"
                    :: "l"(out + (size_t)bat * BSTRIDE + tma_off), "r"(zsm), "n"(4096)
                    : "memory");
            }
            out4[bat * (unsigned)BSTRIDE4 + ebase] = zz;
        }

        const unsigned buf = g & 1;
        #pragma unroll
        for (int nn = 0; nn < NPG; nn++) {
            const unsigned n = g * NPG + nn;
            float4 uv = u_s[buf][nn][tid];                    // LDS.128 (own slot)
            unsigned long long u2[DPT];
            u2[0] = pack2(uv.x, uv.x);
            u2[1] = pack2(uv.y, uv.y);
            u2[2] = pack2(uv.z, uv.z);
            u2[3] = pack2(uv.w, uv.w);
            ulonglong2 alo = a_u2[n * 2 + 0];                 // {b0b1, b2b3}
            ulonglong2 ahi = a_u2[n * 2 + 1];                 // {b4b5, b6b7}
            #pragma unroll
            for (int dd = 0; dd < DPT; dd++) {
                acc[dd][0] = fma2(u2[dd], alo.x, acc[dd][0]);
                acc[dd][1] = fma2(u2[dd], alo.y, acc[dd][1]);
                acc[dd][2] = fma2(u2[dd], ahi.x, acc[dd][2]);
                acc[dd][3] = fma2(u2[dd], ahi.y, acc[dd][3]);
            }
        }
    }

    // ---- epilogue: add mu, transpose pairs, store core (STG.128, coalesced) ----
    const float4 mv = __ldg(&reinterpret_cast<const float4*>(mu)[du]);
    unsigned long long m2[DPT];
    m2[0] = pack2(mv.x, mv.x);
    m2[1] = pack2(mv.y, mv.y);
    m2[2] = pack2(mv.z, mv.z);
    m2[3] = pack2(mv.w, mv.w);

    const unsigned d0 = du * DPT;
    const unsigned k = d0 & 31;                     // multiple of 4
    const unsigned j = (d0 >> 5) & 31;

    const unsigned base = cc * VOL
                        + (ii + POS) * (RES * RES)
                        + (j + POS) * RES
                        + (k + POS)
                        + bg * (unsigned)BSTRIDE;

    #pragma unroll
    for (int p = 0; p < BPB / 2; p++) {
        float lo[DPT], hi[DPT];
        #pragma unroll
        for (int dd = 0; dd < DPT; dd++) {
            unsigned long long r = add2(acc[dd][p], m2[dd]);
            unpack2(r, lo[dd], hi[dd]);
        }
        *reinterpret_cast<float4*>(&out[base + (unsigned)(2 * p + 0) * BSTRIDE]) =
            make_float4(lo[0], lo[1], lo[2], lo[3]);
        *reinterpret_cast<float4*>(&out[base + (unsigned)(2 * p + 1) * BSTRIDE]) =
            make_float4(hi[0], hi[1], hi[2], hi[3]);
    }

    // ---- ensure bulk zero-stores completed before block exit ----
    if (tma_thread) {
        asm volatile("cp.async.bulk.wait_group 0;" ::: "memory");
    }
}

extern "C" void kernel_launch(void* const* d_in, const int* in_sizes, int n_in,
                              void* d_out, int out_size) {
    const float* z  = (const float*)d_in[0];   // (32, 64)
    const float* U  = (const float*)d_in[1];   // (64, 262144)
    const float* L  = (const float*)d_in[2];   // (64,)
    const float* mu = (const float*)d_in[3];   // (262144,)
    float* out = (float*)d_out;                // (32, 8, 64, 64, 64)

    core_part_fused<<<NBLOCKS, TPB>>>(z, U, L, mu, out);
}

// round 16
// speedup vs baseline: 1.1861x; 1.0897x over previous
#include <cuda_runtime.h>
#include <cstdint>

// Problem constants
#define RES    64
#define C_CH   8
#define NB     64
#define CORE   32
#define POS    16                        // (RES-CORE)/2
#define DIM    (CORE*CORE*CORE*C_CH)     // 262144
#define BATCH  32
#define VOL    (RES*RES*RES)             // 262144 floats per (b,c) volume
#define BSTRIDE (C_CH*VOL)               // 2097152 floats per batch
#define BSTRIDE4 (BSTRIDE/4)
#define VOL4     (VOL/4)
#define SLABF   (RES*RES)                // 4096 floats per i-slab

#define TPB 256
#define BPB 8                            // batches per block
#define DPT 4                            // d per thread (16B of U per n)
#define NBLOCKS ((DIM/(TPB*DPT)) * (BATCH/BPB))   // 256 stripes * 4 = 1024

#define NGROUPS 16                       // software-pipeline groups
#define NPG 4                            // n per group (NGROUPS*NPG = 64 = NB)
#define STAGES 3                         // pipeline depth (prefetch distance 2)

// ---- packed fp32x2 helpers (sm_10x FFMA2) ----
__device__ __forceinline__ unsigned long long pack2(float lo, float hi) {
    unsigned long long r;
    asm("mov.b64 %0, {%1, %2};" : "=l"(r) : "f"(lo), "f"(hi));
    return r;
}
__device__ __forceinline__ void unpack2(unsigned long long v, float& lo, float& hi) {
    asm("mov.b64 {%0, %1}, %2;" : "=f"(lo), "=f"(hi) : "l"(v));
}
__device__ __forceinline__ unsigned long long fma2(unsigned long long a,
                                                   unsigned long long b,
                                                   unsigned long long c) {
    unsigned long long r;
    asm("fma.rn.f32x2 %0, %1, %2, %3;" : "=l"(r) : "l"(a), "l"(b), "l"(c));
    return r;
}
__device__ __forceinline__ unsigned long long add2(unsigned long long a,
                                                   unsigned long long b) {
    unsigned long long r;
    asm("add.rn.f32x2 %0, %1, %2;" : "=l"(r) : "l"(a), "l"(b));
    return r;
}

__device__ __forceinline__ void issue_group(unsigned us_base, const float4* Ug,
                                            unsigned g) {
    const unsigned buf = g % STAGES;
    #pragma unroll
    for (int nn = 0; nn < NPG; nn++) {
        asm volatile("cp.async.cg.shared.global [%0], [%1], 16;"
                     :: "r"(us_base + (buf * NPG + nn) * TPB * 16),
                        "l"(Ug + (size_t)(g * NPG + nn) * (DIM / 4)) : "memory");
    }
    asm volatile("cp.async.commit_group;" ::: "memory");
}

// Fused kernel, 3-stage cp.async pipeline:
//   * U streamed global->SMEM with cp.async.cg TWO groups ahead (triple
//     buffer) -> ~300+ cycles of prefetch distance covers L2-hit latency.
//   * accumulators pack BATCH-pairs; a coefficients load as f32x2 from SMEM.
//   * periphery zeroed via cp.async.bulk (4 KB from SMEM zero buffer), one
//     batch's worth every 2 groups -> continuous async write stream.
//   * ragged k-edges: one STG.128/thread every 2 groups.
__global__ __launch_bounds__(TPB, 3)
void core_part_fused(const float* __restrict__ z,
                     const float* __restrict__ U,
                     const float* __restrict__ L,
                     const float* __restrict__ mu,
                     float* __restrict__ out) {
    __shared__ __align__(16) float4 u_s[STAGES][NPG][TPB];  // 48 KB U pipeline
    __shared__ __align__(16) float zbuf[1024];              // 4 KB zeros
    __shared__ __align__(16) float a_s[NB * BPB];           // 2 KB coefficients

    const unsigned tid = threadIdx.x;
    const unsigned stripe = blockIdx.x >> 2;        // 0..255 -> (c, i)
    const unsigned bg     = (blockIdx.x & 3) * BPB; // 0/8/16/24
    const unsigned cc = stripe >> 5;                // channel 0..7
    const unsigned ii = stripe & 31;                // core i 0..31
    const unsigned iful = (ii < 16) ? ii : ii + 32; // adopted full-periphery slab

    const float4 zz = make_float4(0.f, 0.f, 0.f, 0.f);
    float4* out4 = reinterpret_cast<float4*>(out);

    // ---- prologue: stage zeros + coefficients ----
    reinterpret_cast<float4*>(zbuf)[tid] = zz;
    #pragma unroll
    for (unsigned idx = tid; idx < NB * BPB; idx += TPB) {
        unsigned n  = idx >> 3;
        unsigned bl = idx & 7;
        a_s[idx] = L[n] * z[(bg + bl) * NB + n];
    }
    __syncthreads();

    // Per-thread TMA role: threads 0..5 each own one 4 KB periphery piece per batch.
    const unsigned zsm = (unsigned)__cvta_generic_to_shared(zbuf);
    size_t tma_off = 0;
    const bool tma_thread = (tid < 6);
    if (tma_thread) {
        if (tid < 4)       tma_off = (size_t)cc * VOL + iful * SLABF + tid * 1024;
        else if (tid == 4) tma_off = (size_t)cc * VOL + (ii + POS) * SLABF;
        else               tma_off = (size_t)cc * VOL + (ii + POS) * SLABF + 3072;
        asm volatile("fence.proxy.async.shared::cta;" ::: "memory");
    }

    const unsigned du = stripe * TPB + tid;         // f4-index into U row
    const float4* Ug = reinterpret_cast<const float4*>(U) + du;
    const unsigned us_base = (unsigned)__cvta_generic_to_shared(&u_s[0][0][tid]);

    // prime pipeline: groups 0 and 1 in flight
    issue_group(us_base, Ug, 0);
    issue_group(us_base, Ug, 1);

    // accumulators: acc[d][p] = f32x2 {batch bg+2p, batch bg+2p+1}
    unsigned long long acc[DPT][BPB / 2];
    #pragma unroll
    for (int dd = 0; dd < DPT; dd++)
        #pragma unroll
        for (int p = 0; p < BPB / 2; p++) acc[dd][p] = 0ull;

    const ulonglong2* a_u2 = reinterpret_cast<const ulonglong2*>(a_s); // 2 per n

    // k-edge geometry (same every time, batch varies)
    const unsigned erow = tid >> 3;                 // 0..31
    const unsigned eq   = tid & 7;
    const unsigned ek4  = (eq < 4) ? eq : eq + 8;
    const unsigned ebase = cc * (unsigned)VOL4 + (ii + POS) * 1024 + erow * 16 + ek4;

    #pragma unroll
    for (unsigned g = 0; g < NGROUPS; g++) {
        // issue g+2 first, then wait for g (2 newer groups may stay pending)
        if (g + 2 < NGROUPS) {
            issue_group(us_base, Ug, g + 2);
        } else {
            asm volatile("cp.async.commit_group;" ::: "memory");  // keep count uniform
        }
        asm volatile("cp.async.wait_group 2;" ::: "memory");

        // every 2 groups: zero one batch's periphery (TMA bulk) + its k-edges
        if ((g & 1) == 0) {
            const unsigned bat = bg + (g >> 1);
            if (tma_thread) {
                asm volatile(
                    "cp.async.bulk.global.shared::cta.bulk_group [%0], [%1], %2;\n\t"
                    "cp.async.bulk.commit_group;"
                    :: "l"(out + (size_t)bat * BSTRIDE + tma_off), "r"(zsm), "n"(4096)
                    : "memory");
            }
            out4[bat * (unsigned)BSTRIDE4 + ebase] = zz;
        }

        const unsigned buf = g % STAGES;
        #pragma unroll
        for (int nn = 0; nn < NPG; nn++) {
            const unsigned n = g * NPG + nn;
            float4 uv = u_s[buf][nn][tid];                    // LDS.128 (own slot)
            unsigned long long u2[DPT];
            u2[0] = pack2(uv.x, uv.x);
            u2[1] = pack2(uv.y, uv.y);
            u2[2] = pack2(uv.z, uv.z);
            u2[3] = pack2(uv.w, uv.w);
            ulonglong2 alo = a_u2[n * 2 + 0];                 // {b0b1, b2b3}
            ulonglong2 ahi = a_u2[n * 2 + 1];                 // {b4b5, b6b7}
            #pragma unroll
            for (int dd = 0; dd < DPT; dd++) {
                acc[dd][0] = fma2(u2[dd], alo.x, acc[dd][0]);
                acc[dd][1] = fma2(u2[dd], alo.y, acc[dd][1]);
                acc[dd][2] = fma2(u2[dd], ahi.x, acc[dd][2]);
                acc[dd][3] = fma2(u2[dd], ahi.y, acc[dd][3]);
            }
        }
    }

    // ---- epilogue: add mu, transpose pairs, store core (STG.128, coalesced) ----
    const float4 mv = __ldg(&reinterpret_cast<const float4*>(mu)[du]);
    unsigned long long m2[DPT];
    m2[0] = pack2(mv.x, mv.x);
    m2[1] = pack2(mv.y, mv.y);
    m2[2] = pack2(mv.z, mv.z);
    m2[3] = pack2(mv.w, mv.w);

    const unsigned d0 = du * DPT;
    const unsigned k = d0 & 31;                     // multiple of 4
    const unsigned j = (d0 >> 5) & 31;

    const unsigned base = cc * VOL
                        + (ii + POS) * (RES * RES)
                        + (j + POS) * RES
                        + (k + POS)
                        + bg * (unsigned)BSTRIDE;

    #pragma unroll
    for (int p = 0; p < BPB / 2; p++) {
        float lo[DPT], hi[DPT];
        #pragma unroll
        for (int dd = 0; dd < DPT; dd++) {
            unsigned long long r = add2(acc[dd][p], m2[dd]);
            unpack2(r, lo[dd], hi[dd]);
        }
        *reinterpret_cast<float4*>(&out[base + (unsigned)(2 * p + 0) * BSTRIDE]) =
            make_float4(lo[0], lo[1], lo[2], lo[3]);
        *reinterpret_cast<float4*>(&out[base + (unsigned)(2 * p + 1) * BSTRIDE]) =
            make_float4(hi[0], hi[1], hi[2], hi[3]);
    }

    // ---- ensure bulk zero-stores completed before block exit ----
    if (tma_thread) {
        asm volatile("cp.async.bulk.wait_group 0;" ::: "memory");
    }
}

extern "C" void kernel_launch(void* const* d_in, const int* in_sizes, int n_in,
                              void* d_out, int out_size) {
    const float* z  = (const float*)d_in[0];   // (32, 64)
    const float* U  = (const float*)d_in[1];   // (64, 262144)
    const float* L  = (const float*)d_in[2];   // (64,)
    const float* mu = (const float*)d_in[3];   // (262144,)
    float* out = (float*)d_out;                // (32, 8, 64, 64, 64)

    core_part_fused<<<NBLOCKS, TPB>>>(z, U, L, mu, out);
}